// round 4
// baseline (speedup 1.0000x reference)
#include <cuda_runtime.h>
#include <cstdint>
#include <math_constants.h>

#define NN 100000
#define NE 1600000
#define MSORT 131072   // next pow2 >= NN
#define SCB 1024
#define NB  ((NN + SCB - 1) / SCB)   // 98
#define LSPAN 8192     // local bitonic span

// ---------------- scratch (static device globals; no allocations) ----------
__device__ float g_tmp [NN*64];
__device__ float g_bufA[NN*64];
__device__ float g_bufB[NN*64];
__device__ float g_h1  [NN*64];
__device__ float g_h2  [NN*64];
__device__ float g_c1  [NN*64];
__device__ float g_dinv[NN];
__device__ int   g_deg [NN];
__device__ int   g_fill[NN];
__device__ int   g_rowptr[NN+1];
__device__ int   g_part[NB+1];
__device__ int   g_col [NE];
__device__ float g_wgt [NE];
__device__ float g_key [MSORT];
__device__ int   g_sidx[MSORT];
__device__ float g_w1t [5*64*64];
__device__ float g_w2t [5*64*64];

// ---------------- f32x2 packed helpers --------------------------------------
typedef unsigned long long u64;
__device__ __forceinline__ u64 pk2(float a, float b)
{
    u64 r; asm("mov.b64 %0, {%1, %2};" : "=l"(r) : "f"(a), "f"(b)); return r;
}
__device__ __forceinline__ u64 dup2(float a) { return pk2(a, a); }
__device__ __forceinline__ void fma2(u64& d, u64 a, u64 b)
{
    asm("fma.rn.f32x2 %0, %1, %2, %0;" : "+l"(d) : "l"(a), "l"(b));
}
__device__ __forceinline__ float2 up2(u64 v)
{
    float2 f; asm("mov.b64 {%0, %1}, %2;" : "=f"(f.x), "=f"(f.y) : "l"(v)); return f;
}

// ---------------- degree / CSR build ---------------------------------------
__global__ void k_zero()
{
    int i = blockIdx.x*blockDim.x + threadIdx.x;
    if (i < NN) g_deg[i] = 0;
}

__global__ void k_deg(const int* __restrict__ dst)
{
    int e = blockIdx.x*blockDim.x + threadIdx.x;
    if (e < NE) atomicAdd(&g_deg[dst[e]], 1);
}

__global__ void k_scan1()
{
    __shared__ int s[SCB];
    int b = blockIdx.x, t = threadIdx.x;
    int i = b*SCB + t;
    int v = (i < NN) ? g_deg[i] : 0;
    s[t] = v;
    __syncthreads();
#pragma unroll
    for (int off = 1; off < SCB; off <<= 1) {
        int u = (t >= off) ? s[t - off] : 0;
        __syncthreads();
        s[t] += u;
        __syncthreads();
    }
    if (i < NN) g_rowptr[i] = s[t];
    if (t == SCB-1) g_part[b] = s[SCB-1];
}

__global__ void k_scan2()
{
    __shared__ int s[128];
    int t = threadIdx.x;
    int v = (t < NB) ? g_part[t] : 0;
    s[t] = v;
    __syncthreads();
#pragma unroll
    for (int off = 1; off < 128; off <<= 1) {
        int u = (t >= off) ? s[t - off] : 0;
        __syncthreads();
        s[t] += u;
        __syncthreads();
    }
    if (t < NB) g_part[t] = s[t] - v;
}

__global__ void k_scan3()
{
    int b = blockIdx.x, t = threadIdx.x;
    int i = b*SCB + t;
    if (i < NN) {
        int d = g_deg[i];
        g_rowptr[i] = g_rowptr[i] + g_part[b] - d;   // exclusive
        g_fill[i] = 0;
        g_dinv[i] = rsqrtf((float)(d + 1));          // +1 self loop
    }
    if (b == 0 && t == 0) g_rowptr[NN] = NE;
}

__global__ void k_fill(const int* __restrict__ src, const int* __restrict__ dst)
{
    int e = blockIdx.x*blockDim.x + threadIdx.x;
    if (e >= NE) return;
    int d = dst[e], s = src[e];
    int p = g_rowptr[d] + atomicAdd(&g_fill[d], 1);
    g_col[p] = s;
    g_wgt[p] = g_dinv[s] * g_dinv[d];
}

// ---------------- GEMM: C[n,64] = A[n,CI] @ W[CI,64] (f32x2, conflict-free) --
__global__ void k_gemm(const float* __restrict__ A, int CI,
                       const float* __restrict__ W,
                       float* __restrict__ C, int n)
{
    __shared__ float As[64][64];    // [row][k]  (fill: consecutive k per lane)
    __shared__ float Ws[64][64];    // [k][col]
    int tx = threadIdx.x, ty = threadIdx.y;
    int tid = ty*16 + tx;
    int r0 = blockIdx.x * 64;
    u64 acc[4][2] = {};
    int ntiles = CI >> 6;
    for (int kt = 0; kt < ntiles; ++kt) {
        __syncthreads();
        for (int idx = tid; idx < 64*64; idx += 256) {
            int row = idx >> 6, k = idx & 63;
            int gr = r0 + row;
            As[row][k] = (gr < n) ? A[(size_t)gr*CI + kt*64 + k] : 0.f;
        }
        for (int idx = tid; idx < 64*64; idx += 256) {
            int kr = idx >> 6, c = idx & 63;
            Ws[kr][c] = W[(size_t)(kt*64 + kr)*64 + c];
        }
        __syncthreads();
#pragma unroll 4
        for (int k4 = 0; k4 < 64; k4 += 4) {
            float4 a0 = *reinterpret_cast<const float4*>(&As[ty*4+0][k4]);
            float4 a1 = *reinterpret_cast<const float4*>(&As[ty*4+1][k4]);
            float4 a2 = *reinterpret_cast<const float4*>(&As[ty*4+2][k4]);
            float4 a3 = *reinterpret_cast<const float4*>(&As[ty*4+3][k4]);
            float ar0[4] = {a0.x,a0.y,a0.z,a0.w};
            float ar1[4] = {a1.x,a1.y,a1.z,a1.w};
            float ar2[4] = {a2.x,a2.y,a2.z,a2.w};
            float ar3[4] = {a3.x,a3.y,a3.z,a3.w};
#pragma unroll
            for (int kk = 0; kk < 4; ++kk) {
                ulonglong2 w = *reinterpret_cast<const ulonglong2*>(&Ws[k4+kk][tx*4]);
                u64 b0 = dup2(ar0[kk]), b1 = dup2(ar1[kk]);
                u64 b2 = dup2(ar2[kk]), b3 = dup2(ar3[kk]);
                fma2(acc[0][0], b0, w.x); fma2(acc[0][1], b0, w.y);
                fma2(acc[1][0], b1, w.x); fma2(acc[1][1], b1, w.y);
                fma2(acc[2][0], b2, w.x); fma2(acc[2][1], b2, w.y);
                fma2(acc[3][0], b3, w.x); fma2(acc[3][1], b3, w.y);
            }
        }
    }
#pragma unroll
    for (int i = 0; i < 4; ++i) {
        int gr = r0 + ty*4 + i;
        if (gr < n) {
            float2 lo = up2(acc[i][0]), hi = up2(acc[i][1]);
            float4 o = make_float4(lo.x, lo.y, hi.x, hi.y);
            *reinterpret_cast<float4*>(&C[(size_t)gr*64 + tx*4]) = o;
        }
    }
}

// ---------------- GCN aggregation (warp per node, float2 lanes) --------------
__global__ void k_agg(const float* __restrict__ T, const float* __restrict__ b,
                      float* __restrict__ O, int relu, int n)
{
    int w    = (blockIdx.x*blockDim.x + threadIdx.x) >> 5;
    int lane = threadIdx.x & 31;
    if (w >= n) return;
    const float2* T2 = reinterpret_cast<const float2*>(T);
    int s = g_rowptr[w], e = g_rowptr[w+1];
    float a0 = 0.f, a1 = 0.f;
    int j = s;
    for (; j + 4 <= e; j += 4) {
        int   c0 = g_col[j],  c1 = g_col[j+1],  c2 = g_col[j+2],  c3 = g_col[j+3];
        float w0 = g_wgt[j],  w1 = g_wgt[j+1],  w2 = g_wgt[j+2],  w3 = g_wgt[j+3];
        float2 t0 = T2[(size_t)c0*32 + lane];
        float2 t1 = T2[(size_t)c1*32 + lane];
        float2 t2 = T2[(size_t)c2*32 + lane];
        float2 t3 = T2[(size_t)c3*32 + lane];
        a0 += w0*t0.x + w1*t1.x + w2*t2.x + w3*t3.x;
        a1 += w0*t0.y + w1*t1.y + w2*t2.y + w3*t3.y;
    }
    for (; j < e; ++j) {
        int c = g_col[j]; float ww = g_wgt[j];
        float2 t = T2[(size_t)c*32 + lane];
        a0 += ww * t.x;
        a1 += ww * t.y;
    }
    float di = g_dinv[w]; float sw = di*di;
    float2 ts = T2[(size_t)w*32 + lane];
    a0 += sw * ts.x;
    a1 += sw * ts.y;
    float2 bb = reinterpret_cast<const float2*>(b)[lane];
    a0 += bb.x;
    a1 += bb.y;
    if (relu) { a0 = fmaxf(a0, 0.f); a1 = fmaxf(a1, 0.f); }
    reinterpret_cast<float2*>(O)[(size_t)w*32 + lane] = make_float2(a0, a1);
}

// ---------------- scores + sort init ----------------------------------------
__global__ void k_score(const float* __restrict__ Wp, const float* __restrict__ bp, int n)
{
    int gw   = (blockIdx.x*blockDim.x + threadIdx.x) >> 5;
    int lane = threadIdx.x & 31;
    if (gw >= MSORT) return;
    if (gw < n) {
        float2 h = reinterpret_cast<const float2*>(g_h1)[(size_t)gw*32 + lane];
        float2 wp = reinterpret_cast<const float2*>(Wp)[lane];
        float p = h.x*wp.x + h.y*wp.y;
#pragma unroll
        for (int o = 16; o; o >>= 1) p += __shfl_xor_sync(0xffffffffu, p, o);
        if (lane == 0) { g_key[gw] = p + bp[0]; g_sidx[gw] = gw; }
    } else {
        if (lane == 0) { g_key[gw] = CUDART_INF_F; g_sidx[gw] = gw; }
    }
}

// ---------------- bitonic sort (stable via index tie-break) ------------------
__device__ __forceinline__ bool cmp_gt(float ka, int ia, float kb, int ib)
{
    return (ka > kb) || (ka == kb && ia > ib);
}

// local sort of LSPAN-element chunks (8 elems/thread, 64KB dynamic smem)
__global__ void k_localsort8()
{
    extern __shared__ float sm8[];
    float* sk = sm8;
    int*   si = reinterpret_cast<int*>(sm8 + LSPAN);
    int t = threadIdx.x;
    int base = blockIdx.x * LSPAN;
#pragma unroll
    for (int m = 0; m < 8; ++m) {
        sk[t + m*1024] = g_key[base + t + m*1024];
        si[t + m*1024] = g_sidx[base + t + m*1024];
    }
    for (int k = 2; k <= LSPAN; k <<= 1) {
        for (int j = k >> 1; j > 0; j >>= 1) {
            __syncthreads();
#pragma unroll
            for (int m = 0; m < 4; ++m) {
                int idx = t + m*1024;                 // pair index < LSPAN/2
                int i = ((idx & ~(j-1)) << 1) | (idx & (j-1));
                int p = i + j;
                bool asc = (((base + i) & k) == 0);
                float ki = sk[i], kp = sk[p];
                int   xi = si[i], xp = si[p];
                if (cmp_gt(ki, xi, kp, xp) == asc) {
                    sk[i] = kp; sk[p] = ki; si[i] = xp; si[p] = xi;
                }
            }
        }
    }
    __syncthreads();
#pragma unroll
    for (int m = 0; m < 8; ++m) {
        g_key[base + t + m*1024]  = sk[t + m*1024];
        g_sidx[base + t + m*1024] = si[t + m*1024];
    }
}

__global__ void k_globalpass(int k, int j)
{
    int t = blockIdx.x*blockDim.x + threadIdx.x;   // < MSORT/2
    int i = ((t & ~(j-1)) << 1) | (t & (j-1));
    int p = i + j;
    bool asc = ((i & k) == 0);
    float ki = g_key[i], kp = g_key[p];
    int   xi = g_sidx[i], xp = g_sidx[p];
    if (cmp_gt(ki, xi, kp, xp) == asc) {
        g_key[i] = kp; g_key[p] = ki; g_sidx[i] = xp; g_sidx[p] = xi;
    }
}

// in-smem merge for j <= LSPAN/2 (k >= 2*LSPAN so asc is block-constant)
__global__ void k_merge8(int k)
{
    extern __shared__ float sm8[];
    float* sk = sm8;
    int*   si = reinterpret_cast<int*>(sm8 + LSPAN);
    int t = threadIdx.x;
    int base = blockIdx.x * LSPAN;
#pragma unroll
    for (int m = 0; m < 8; ++m) {
        sk[t + m*1024] = g_key[base + t + m*1024];
        si[t + m*1024] = g_sidx[base + t + m*1024];
    }
    bool asc = ((base & k) == 0);
    for (int j = LSPAN/2; j > 0; j >>= 1) {
        __syncthreads();
#pragma unroll
        for (int m = 0; m < 4; ++m) {
            int idx = t + m*1024;
            int i = ((idx & ~(j-1)) << 1) | (idx & (j-1));
            int p = i + j;
            float ki = sk[i], kp = sk[p];
            int   xi = si[i], xp = si[p];
            if (cmp_gt(ki, xi, kp, xp) == asc) {
                sk[i] = kp; sk[p] = ki; si[i] = xp; si[p] = xi;
            }
        }
    }
    __syncthreads();
#pragma unroll
    for (int m = 0; m < 8; ++m) {
        g_key[base + t + m*1024]  = sk[t + m*1024];
        g_sidx[base + t + m*1024] = si[t + m*1024];
    }
}

// ---------------- conv weight transpose: [co][ci][k] -> [k][ci][co] ----------
__global__ void k_transw(const float* __restrict__ w1, const float* __restrict__ w2)
{
    int t = blockIdx.x*blockDim.x + threadIdx.x;
    if (t >= 2*5*64*64) return;
    int which = t >= 5*64*64;
    int u = t - which*5*64*64;
    int co = u & 63;
    int ci = (u >> 6) & 63;
    int kk = u >> 12;
    float v = which ? w2[co*320 + ci*5 + kk] : w1[co*320 + ci*5 + kk];
    if (which) g_w2t[u] = v; else g_w1t[u] = v;
}

// ---------------- conv1d over ranks (K=5, pad=2, f32x2, all taps resident) ---
// gather=1: input row r is g_key[r] * g_h1[g_sidx[r]][ci]  (fused buildsx)
__global__ void k_conv(const float* __restrict__ X, const float* __restrict__ Wt,
                       const float* __restrict__ b, float* __restrict__ Y,
                       const int* __restrict__ scat, int relu, int gather, int n)
{
    extern __shared__ float cs[];
    float (*xs)[64] = reinterpret_cast<float(*)[64]>(cs);            // [68][64]
    float (*ws)[64] = reinterpret_cast<float(*)[64]>(cs + 68*64);    // [320][64]
    int tx = threadIdx.x, ty = threadIdx.y;
    int tid = ty*16 + tx;
    int r0 = blockIdx.x * 64;
    for (int idx = tid; idx < 68*64; idx += 256) {
        int rl = idx >> 6, ci = idx & 63;
        int r = r0 - 2 + rl;
        float v = 0.f;
        if (r >= 0 && r < n) {
            if (gather) v = g_key[r] * g_h1[(size_t)g_sidx[r]*64 + ci];
            else        v = X[(size_t)r*64 + ci];
        }
        xs[rl][ci] = v;
    }
    for (int idx = tid; idx < 5*64*64; idx += 256)
        ws[idx >> 6][idx & 63] = Wt[idx];
    __syncthreads();
    u64 acc[4][2] = {};
#pragma unroll
    for (int k = 0; k < 5; ++k) {
#pragma unroll 4
        for (int c4 = 0; c4 < 64; c4 += 4) {
            float4 a0 = *reinterpret_cast<const float4*>(&xs[ty*4+0+k][c4]);
            float4 a1 = *reinterpret_cast<const float4*>(&xs[ty*4+1+k][c4]);
            float4 a2 = *reinterpret_cast<const float4*>(&xs[ty*4+2+k][c4]);
            float4 a3 = *reinterpret_cast<const float4*>(&xs[ty*4+3+k][c4]);
            float ar0[4] = {a0.x,a0.y,a0.z,a0.w};
            float ar1[4] = {a1.x,a1.y,a1.z,a1.w};
            float ar2[4] = {a2.x,a2.y,a2.z,a2.w};
            float ar3[4] = {a3.x,a3.y,a3.z,a3.w};
#pragma unroll
            for (int cc = 0; cc < 4; ++cc) {
                ulonglong2 w = *reinterpret_cast<const ulonglong2*>(&ws[k*64 + c4 + cc][tx*4]);
                u64 b0 = dup2(ar0[cc]), b1 = dup2(ar1[cc]);
                u64 b2 = dup2(ar2[cc]), b3 = dup2(ar3[cc]);
                fma2(acc[0][0], b0, w.x); fma2(acc[0][1], b0, w.y);
                fma2(acc[1][0], b1, w.x); fma2(acc[1][1], b1, w.y);
                fma2(acc[2][0], b2, w.x); fma2(acc[2][1], b2, w.y);
                fma2(acc[3][0], b3, w.x); fma2(acc[3][1], b3, w.y);
            }
        }
    }
#pragma unroll
    for (int i = 0; i < 4; ++i) {
        int r = r0 + ty*4 + i;
        if (r < n) {
            int orow = scat ? scat[r] : r;
            float2 lo = up2(acc[i][0]), hi = up2(acc[i][1]);
            float4 o;
            o.x = lo.x + b[tx*4 + 0];
            o.y = lo.y + b[tx*4 + 1];
            o.z = hi.x + b[tx*4 + 2];
            o.w = hi.y + b[tx*4 + 3];
            if (relu) {
                o.x = fmaxf(o.x, 0.f); o.y = fmaxf(o.y, 0.f);
                o.z = fmaxf(o.z, 0.f); o.w = fmaxf(o.w, 0.f);
            }
            *reinterpret_cast<float4*>(&Y[(size_t)orow*64 + tx*4]) = o;
        }
    }
}

// ---------------- final linear: out = [h1|h2] @ lin_w + lin_b (f32x2) --------
__global__ void k_lin(const float* __restrict__ A0, const float* __restrict__ A1,
                      const float* __restrict__ W, const float* __restrict__ b,
                      float* __restrict__ C, int n)
{
    __shared__ float As[64][64];
    __shared__ float Ws[64][64];
    int tx = threadIdx.x, ty = threadIdx.y;
    int tid = ty*16 + tx;
    int r0 = blockIdx.x * 64;
    u64 acc[4][2] = {};
    for (int kt = 0; kt < 2; ++kt) {
        const float* A = (kt == 0) ? A0 : A1;
        __syncthreads();
        for (int idx = tid; idx < 64*64; idx += 256) {
            int row = idx >> 6, k = idx & 63;
            int gr = r0 + row;
            As[row][k] = (gr < n) ? A[(size_t)gr*64 + k] : 0.f;
        }
        for (int idx = tid; idx < 64*64; idx += 256) {
            int kr = idx >> 6, c = idx & 63;
            Ws[kr][c] = W[(size_t)(kt*64 + kr)*64 + c];
        }
        __syncthreads();
#pragma unroll 4
        for (int k4 = 0; k4 < 64; k4 += 4) {
            float4 a0 = *reinterpret_cast<const float4*>(&As[ty*4+0][k4]);
            float4 a1 = *reinterpret_cast<const float4*>(&As[ty*4+1][k4]);
            float4 a2 = *reinterpret_cast<const float4*>(&As[ty*4+2][k4]);
            float4 a3 = *reinterpret_cast<const float4*>(&As[ty*4+3][k4]);
            float ar0[4] = {a0.x,a0.y,a0.z,a0.w};
            float ar1[4] = {a1.x,a1.y,a1.z,a1.w};
            float ar2[4] = {a2.x,a2.y,a2.z,a2.w};
            float ar3[4] = {a3.x,a3.y,a3.z,a3.w};
#pragma unroll
            for (int kk = 0; kk < 4; ++kk) {
                ulonglong2 w = *reinterpret_cast<const ulonglong2*>(&Ws[k4+kk][tx*4]);
                u64 b0 = dup2(ar0[kk]), b1 = dup2(ar1[kk]);
                u64 b2 = dup2(ar2[kk]), b3 = dup2(ar3[kk]);
                fma2(acc[0][0], b0, w.x); fma2(acc[0][1], b0, w.y);
                fma2(acc[1][0], b1, w.x); fma2(acc[1][1], b1, w.y);
                fma2(acc[2][0], b2, w.x); fma2(acc[2][1], b2, w.y);
                fma2(acc[3][0], b3, w.x); fma2(acc[3][1], b3, w.y);
            }
        }
    }
#pragma unroll
    for (int i = 0; i < 4; ++i) {
        int gr = r0 + ty*4 + i;
        if (gr < n) {
            float2 lo = up2(acc[i][0]), hi = up2(acc[i][1]);
            float4 o;
            o.x = lo.x + b[tx*4 + 0];
            o.y = lo.y + b[tx*4 + 1];
            o.z = hi.x + b[tx*4 + 2];
            o.w = hi.y + b[tx*4 + 3];
            *reinterpret_cast<float4*>(&C[(size_t)gr*64 + tx*4]) = o;
        }
    }
}

// ---------------- host launcher ---------------------------------------------
extern "C" void kernel_launch(void* const* d_in, const int* in_sizes, int n_in,
                              void* d_out, int out_size)
{
    const float* x   = (const float*)d_in[0];
    const int*   ei  = (const int*)  d_in[1];
    const float* W0  = (const float*)d_in[2];
    const float* b0  = (const float*)d_in[3];
    const float* W1  = (const float*)d_in[4];
    const float* b1  = (const float*)d_in[5];
    const float* W2  = (const float*)d_in[6];
    const float* b2  = (const float*)d_in[7];
    const float* Wp  = (const float*)d_in[8];
    const float* bp  = (const float*)d_in[9];
    const float* c1w = (const float*)d_in[10];
    const float* c1b = (const float*)d_in[11];
    const float* c2w = (const float*)d_in[12];
    const float* c2b = (const float*)d_in[13];
    const float* lw  = (const float*)d_in[14];
    const float* lb  = (const float*)d_in[15];
    float* out = (float*)d_out;

    const int n = NN, E = NE;
    const int* src = ei;
    const int* dst = ei + E;

    float *p_tmp, *p_bufA, *p_bufB, *p_h1, *p_h2, *p_c1, *p_w1t, *p_w2t;
    int *p_sidx;
    cudaGetSymbolAddress((void**)&p_tmp,  g_tmp);
    cudaGetSymbolAddress((void**)&p_bufA, g_bufA);
    cudaGetSymbolAddress((void**)&p_bufB, g_bufB);
    cudaGetSymbolAddress((void**)&p_h1,   g_h1);
    cudaGetSymbolAddress((void**)&p_h2,   g_h2);
    cudaGetSymbolAddress((void**)&p_c1,   g_c1);
    cudaGetSymbolAddress((void**)&p_w1t,  g_w1t);
    cudaGetSymbolAddress((void**)&p_w2t,  g_w2t);
    cudaGetSymbolAddress((void**)&p_sidx, g_sidx);

    const int CONV_SMEM = (68*64 + 5*64*64) * 4;   // 99,328 B
    const int SORT_SMEM = LSPAN * 8;               // 65,536 B
    cudaFuncSetAttribute(k_conv,       cudaFuncAttributeMaxDynamicSharedMemorySize, CONV_SMEM);
    cudaFuncSetAttribute(k_localsort8, cudaFuncAttributeMaxDynamicSharedMemorySize, SORT_SMEM);
    cudaFuncSetAttribute(k_merge8,     cudaFuncAttributeMaxDynamicSharedMemorySize, SORT_SMEM);

    // ---- degree + CSR build (multi-block scan) ----
    k_zero <<<(n + 255)/256, 256>>>();
    k_deg  <<<(E + 255)/256, 256>>>(dst);
    k_scan1<<<NB, SCB>>>();
    k_scan2<<<1, 128>>>();
    k_scan3<<<NB, SCB>>>();
    k_fill <<<(E + 255)/256, 256>>>(src, dst);

    dim3 tg(16, 16);
    int  gb = (n + 63) / 64;
    int  ab = (n + 7) / 8;     // warp per node, 8 warps/block

    // ---- 3 GCN layers ----
    k_gemm<<<gb, tg>>>(x, 128, W0, p_tmp, n);
    k_agg <<<ab, 256>>>(p_tmp, b0, p_bufA, 1, n);
    k_gemm<<<gb, tg>>>(p_bufA, 64, W1, p_tmp, n);
    k_agg <<<ab, 256>>>(p_tmp, b1, p_bufB, 1, n);
    k_gemm<<<gb, tg>>>(p_bufB, 64, W2, p_tmp, n);
    k_agg <<<ab, 256>>>(p_tmp, b2, p_h1, 0, n);

    // ---- scores + stable bitonic argsort (8192-span local, 15 launches) ----
    k_score<<<MSORT/8, 256>>>(Wp, bp, n);
    k_localsort8<<<MSORT/LSPAN, 1024, SORT_SMEM>>>();
    for (int k = 2*LSPAN; k <= MSORT; k <<= 1) {
        for (int j = k >> 1; j >= LSPAN; j >>= 1)
            k_globalpass<<<MSORT/2048, 1024>>>(k, j);
        k_merge8<<<MSORT/LSPAN, 1024, SORT_SMEM>>>(k);
    }

    // ---- weight transpose, convs (conv1 gathers sorted_x on the fly,
    //      conv2 scatters back to node order), final linear ----
    k_transw<<<(2*5*64*64 + 255)/256, 256>>>(c1w, c2w);
    k_conv<<<gb, tg, CONV_SMEM>>>(nullptr, p_w1t, c1b, p_c1, nullptr, 1, 1, n);
    k_conv<<<gb, tg, CONV_SMEM>>>(p_c1,    p_w2t, c2b, p_h2, p_sidx, 0, 0, n);
    k_lin<<<gb, tg>>>(p_h1, p_h2, lw, lb, out, n);
}

// round 5
// speedup vs baseline: 1.0636x; 1.0636x over previous
#include <cuda_runtime.h>
#include <cstdint>
#include <math_constants.h>

#define NN 100000
#define NE 1600000
#define MSORT 131072   // next pow2 >= NN
#define SCB 1024
#define NB  ((NN + SCB - 1) / SCB)   // 98

// ---------------- scratch (static device globals; no allocations) ----------
__device__ float g_tmp [NN*64];
__device__ float g_bufA[NN*64];
__device__ float g_bufB[NN*64];
__device__ float g_h1  [NN*64];
__device__ float g_h2  [NN*64];
__device__ float g_c1  [NN*64];
__device__ float g_dinv[NN];
__device__ int   g_deg [NN];
__device__ int   g_fill[NN];
__device__ int   g_rowptr[NN+1];
__device__ int   g_part[NB+1];
__device__ int   g_col [NE];
__device__ float g_wgt [NE];
__device__ float g_key [MSORT];
__device__ int   g_sidx[MSORT];
__device__ float g_w1t [5*64*64];
__device__ float g_w2t [5*64*64];

// ---------------- f32x2 packed helpers --------------------------------------
typedef unsigned long long u64;
__device__ __forceinline__ u64 pk2(float a, float b)
{
    u64 r; asm("mov.b64 %0, {%1, %2};" : "=l"(r) : "f"(a), "f"(b)); return r;
}
__device__ __forceinline__ u64 dup2(float a) { return pk2(a, a); }
__device__ __forceinline__ void fma2(u64& d, u64 a, u64 b)
{
    asm("fma.rn.f32x2 %0, %1, %2, %0;" : "+l"(d) : "l"(a), "l"(b));
}
__device__ __forceinline__ float2 up2(u64 v)
{
    float2 f; asm("mov.b64 {%0, %1}, %2;" : "=f"(f.x), "=f"(f.y) : "l"(v)); return f;
}

// ---------------- degree / CSR build ---------------------------------------
__global__ void k_zero()
{
    int i = blockIdx.x*blockDim.x + threadIdx.x;
    if (i < NN) g_deg[i] = 0;
}

__global__ void k_deg(const int* __restrict__ dst)
{
    int e = blockIdx.x*blockDim.x + threadIdx.x;
    if (e < NE) atomicAdd(&g_deg[dst[e]], 1);
}

__global__ void k_scan1()
{
    __shared__ int s[SCB];
    int b = blockIdx.x, t = threadIdx.x;
    int i = b*SCB + t;
    int v = (i < NN) ? g_deg[i] : 0;
    s[t] = v;
    __syncthreads();
#pragma unroll
    for (int off = 1; off < SCB; off <<= 1) {
        int u = (t >= off) ? s[t - off] : 0;
        __syncthreads();
        s[t] += u;
        __syncthreads();
    }
    if (i < NN) g_rowptr[i] = s[t];
    if (t == SCB-1) g_part[b] = s[SCB-1];
}

__global__ void k_scan2()
{
    __shared__ int s[128];
    int t = threadIdx.x;
    int v = (t < NB) ? g_part[t] : 0;
    s[t] = v;
    __syncthreads();
#pragma unroll
    for (int off = 1; off < 128; off <<= 1) {
        int u = (t >= off) ? s[t - off] : 0;
        __syncthreads();
        s[t] += u;
        __syncthreads();
    }
    if (t < NB) g_part[t] = s[t] - v;
}

__global__ void k_scan3()
{
    int b = blockIdx.x, t = threadIdx.x;
    int i = b*SCB + t;
    if (i < NN) {
        int d = g_deg[i];
        g_rowptr[i] = g_rowptr[i] + g_part[b] - d;   // exclusive
        g_fill[i] = 0;
        g_dinv[i] = rsqrtf((float)(d + 1));          // +1 self loop
    }
    if (b == 0 && t == 0) g_rowptr[NN] = NE;
}

// pad sort keys [NN, MSORT) with +INF (independent of everything else)
__global__ void k_pad()
{
    int i = NN + blockIdx.x*blockDim.x + threadIdx.x;
    if (i < MSORT) { g_key[i] = CUDART_INF_F; g_sidx[i] = i; }
}

__global__ void k_fill(const int* __restrict__ src, const int* __restrict__ dst)
{
    int e = blockIdx.x*blockDim.x + threadIdx.x;
    if (e >= NE) return;
    int d = dst[e], s = src[e];
    int p = g_rowptr[d] + atomicAdd(&g_fill[d], 1);
    g_col[p] = s;
    g_wgt[p] = g_dinv[s] * g_dinv[d];
}

// ---------------- GEMM: C[n,64] = A[n,CI] @ W[CI,64] (f32x2) ----------------
__global__ void k_gemm(const float* __restrict__ A, int CI,
                       const float* __restrict__ W,
                       float* __restrict__ C, int n)
{
    __shared__ float As[64][72];    // [k][row]
    __shared__ float Ws[64][64];    // [k][col]
    int tx = threadIdx.x, ty = threadIdx.y;
    int tid = ty*16 + tx;
    int r0 = blockIdx.x * 64;
    u64 acc[4][2] = {};
    int ntiles = CI >> 6;
    for (int kt = 0; kt < ntiles; ++kt) {
        __syncthreads();
        for (int idx = tid; idx < 64*64; idx += 256) {
            int row = idx >> 6, k = idx & 63;
            int gr = r0 + row;
            As[k][row] = (gr < n) ? A[(size_t)gr*CI + kt*64 + k] : 0.f;
        }
        for (int idx = tid; idx < 64*64; idx += 256) {
            int kr = idx >> 6, c = idx & 63;
            Ws[kr][c] = W[(size_t)(kt*64 + kr)*64 + c];
        }
        __syncthreads();
#pragma unroll 8
        for (int k = 0; k < 64; ++k) {
            float4 a = *reinterpret_cast<const float4*>(&As[k][ty*4]);
            ulonglong2 w = *reinterpret_cast<const ulonglong2*>(&Ws[k][tx*4]);
            u64 a0 = dup2(a.x), a1 = dup2(a.y), a2 = dup2(a.z), a3 = dup2(a.w);
            fma2(acc[0][0], a0, w.x); fma2(acc[0][1], a0, w.y);
            fma2(acc[1][0], a1, w.x); fma2(acc[1][1], a1, w.y);
            fma2(acc[2][0], a2, w.x); fma2(acc[2][1], a2, w.y);
            fma2(acc[3][0], a3, w.x); fma2(acc[3][1], a3, w.y);
        }
    }
#pragma unroll
    for (int i = 0; i < 4; ++i) {
        int gr = r0 + ty*4 + i;
        if (gr < n) {
            float2 lo = up2(acc[i][0]), hi = up2(acc[i][1]);
            float4 o = make_float4(lo.x, lo.y, hi.x, hi.y);
            *reinterpret_cast<float4*>(&C[(size_t)gr*64 + tx*4]) = o;
        }
    }
}

// ---------------- GCN aggregation (warp per node, float2 lanes) --------------
// score != nullptr (last layer): also compute g_key[w] = h1[w].Wp + bp, g_sidx.
__global__ void k_agg(const float* __restrict__ T, const float* __restrict__ b,
                      float* __restrict__ O, int relu, int n,
                      const float* __restrict__ score_w, const float* __restrict__ score_b)
{
    int w    = (blockIdx.x*blockDim.x + threadIdx.x) >> 5;
    int lane = threadIdx.x & 31;
    if (w >= n) return;
    const float2* T2 = reinterpret_cast<const float2*>(T);
    int s = g_rowptr[w], e = g_rowptr[w+1];
    float a0 = 0.f, a1 = 0.f;
    int j = s;
    for (; j + 4 <= e; j += 4) {
        int   c0 = g_col[j],  c1 = g_col[j+1],  c2 = g_col[j+2],  c3 = g_col[j+3];
        float w0 = g_wgt[j],  w1 = g_wgt[j+1],  w2 = g_wgt[j+2],  w3 = g_wgt[j+3];
        float2 t0 = T2[(size_t)c0*32 + lane];
        float2 t1 = T2[(size_t)c1*32 + lane];
        float2 t2 = T2[(size_t)c2*32 + lane];
        float2 t3 = T2[(size_t)c3*32 + lane];
        a0 += w0*t0.x + w1*t1.x + w2*t2.x + w3*t3.x;
        a1 += w0*t0.y + w1*t1.y + w2*t2.y + w3*t3.y;
    }
    for (; j < e; ++j) {
        int c = g_col[j]; float ww = g_wgt[j];
        float2 t = T2[(size_t)c*32 + lane];
        a0 += ww * t.x;
        a1 += ww * t.y;
    }
    float di = g_dinv[w]; float sw = di*di;
    float2 ts = T2[(size_t)w*32 + lane];
    a0 += sw * ts.x;
    a1 += sw * ts.y;
    float2 bb = reinterpret_cast<const float2*>(b)[lane];
    a0 += bb.x;
    a1 += bb.y;
    if (relu) { a0 = fmaxf(a0, 0.f); a1 = fmaxf(a1, 0.f); }
    reinterpret_cast<float2*>(O)[(size_t)w*32 + lane] = make_float2(a0, a1);
    if (score_w) {
        float2 wp = reinterpret_cast<const float2*>(score_w)[lane];
        float p = a0*wp.x + a1*wp.y;
#pragma unroll
        for (int o = 16; o; o >>= 1) p += __shfl_xor_sync(0xffffffffu, p, o);
        if (lane == 0) { g_key[w] = p + score_b[0]; g_sidx[w] = w; }
    }
}

// ---------------- bitonic sort (stable via index tie-break) ------------------
__device__ __forceinline__ bool cmp_gt(float ka, int ia, float kb, int ib)
{
    return (ka > kb) || (ka == kb && ia > ib);
}

__global__ void k_localsort()
{
    __shared__ float sk[2048];
    __shared__ int   si[2048];
    int t = threadIdx.x;
    int base = blockIdx.x * 2048;
    sk[t]        = g_key[base + t];        si[t]        = g_sidx[base + t];
    sk[t + 1024] = g_key[base + t + 1024]; si[t + 1024] = g_sidx[base + t + 1024];
    for (int k = 2; k <= 2048; k <<= 1) {
        for (int j = k >> 1; j > 0; j >>= 1) {
            __syncthreads();
            int i = ((t & ~(j-1)) << 1) | (t & (j-1));
            int p = i + j;
            bool asc = (((base + i) & k) == 0);
            float ki = sk[i], kp = sk[p];
            int   xi = si[i], xp = si[p];
            if (cmp_gt(ki, xi, kp, xp) == asc) {
                sk[i] = kp; sk[p] = ki; si[i] = xp; si[p] = xi;
            }
        }
    }
    __syncthreads();
    g_key[base + t]        = sk[t];        g_sidx[base + t]        = si[t];
    g_key[base + t + 1024] = sk[t + 1024]; g_sidx[base + t + 1024] = si[t + 1024];
}

__global__ void k_globalpass(int k, int j)
{
    int t = blockIdx.x*blockDim.x + threadIdx.x;   // < MSORT/2
    int i = ((t & ~(j-1)) << 1) | (t & (j-1));
    int p = i + j;
    bool asc = ((i & k) == 0);
    float ki = g_key[i], kp = g_key[p];
    int   xi = g_sidx[i], xp = g_sidx[p];
    if (cmp_gt(ki, xi, kp, xp) == asc) {
        g_key[i] = kp; g_key[p] = ki; g_sidx[i] = xp; g_sidx[p] = xi;
    }
}

__global__ void k_mergeshared(int k)
{
    __shared__ float sk[2048];
    __shared__ int   si[2048];
    int t = threadIdx.x;
    int base = blockIdx.x * 2048;
    sk[t]        = g_key[base + t];        si[t]        = g_sidx[base + t];
    sk[t + 1024] = g_key[base + t + 1024]; si[t + 1024] = g_sidx[base + t + 1024];
    bool asc = ((base & k) == 0);          // k >= 4096: constant per 2048-chunk
    for (int j = 1024; j > 0; j >>= 1) {
        __syncthreads();
        int i = ((t & ~(j-1)) << 1) | (t & (j-1));
        int p = i + j;
        float ki = sk[i], kp = sk[p];
        int   xi = si[i], xp = si[p];
        if (cmp_gt(ki, xi, kp, xp) == asc) {
            sk[i] = kp; sk[p] = ki; si[i] = xp; si[p] = xi;
        }
    }
    __syncthreads();
    g_key[base + t]        = sk[t];        g_sidx[base + t]        = si[t];
    g_key[base + t + 1024] = sk[t + 1024]; g_sidx[base + t + 1024] = si[t + 1024];
}

// ---------------- conv weight transpose: [co][ci][k] -> [k][ci][co] ----------
__global__ void k_transw(const float* __restrict__ w, float* __restrict__ wt)
{
    int t = blockIdx.x*blockDim.x + threadIdx.x;
    if (t >= 5*64*64) return;
    int co = t & 63;
    int ci = (t >> 6) & 63;
    int kk = t >> 12;
    wt[t] = w[co*320 + ci*5 + kk];
}

// ---------------- conv1d over ranks (K=5, pad=2, f32x2) ----------------------
// gather=1: input row r is g_key[r] * g_h1[g_sidx[r]][ci]  (fused buildsx)
__global__ void k_conv(const float* __restrict__ X, const float* __restrict__ Wt,
                       const float* __restrict__ b, float* __restrict__ Y,
                       const int* __restrict__ scat, int relu, int gather, int n)
{
    __shared__ float xs[64][72];   // [ci][rl], rl covers rows r0-2 .. r0+65
    __shared__ float ws[64][64];   // [ci][co] for current tap k
    int tx = threadIdx.x, ty = threadIdx.y;
    int tid = ty*16 + tx;
    int r0 = blockIdx.x * 64;
    for (int idx = tid; idx < 68*64; idx += 256) {
        int rl = idx >> 6, ci = idx & 63;
        int r = r0 - 2 + rl;
        float v = 0.f;
        if (r >= 0 && r < n) {
            if (gather) v = g_key[r] * g_h1[(size_t)g_sidx[r]*64 + ci];
            else        v = X[(size_t)r*64 + ci];
        }
        xs[ci][rl] = v;
    }
    u64 acc[4][2] = {};
    for (int k = 0; k < 5; ++k) {
        __syncthreads();
        for (int idx = tid; idx < 4096; idx += 256)
            ws[idx >> 6][idx & 63] = Wt[k*4096 + idx];
        __syncthreads();
#pragma unroll 4
        for (int ci = 0; ci < 64; ++ci) {
            ulonglong2 w = *reinterpret_cast<const ulonglong2*>(&ws[ci][tx*4]);
            u64 a0 = dup2(xs[ci][ty*4 + 0 + k]);
            u64 a1 = dup2(xs[ci][ty*4 + 1 + k]);
            u64 a2 = dup2(xs[ci][ty*4 + 2 + k]);
            u64 a3 = dup2(xs[ci][ty*4 + 3 + k]);
            fma2(acc[0][0], a0, w.x); fma2(acc[0][1], a0, w.y);
            fma2(acc[1][0], a1, w.x); fma2(acc[1][1], a1, w.y);
            fma2(acc[2][0], a2, w.x); fma2(acc[2][1], a2, w.y);
            fma2(acc[3][0], a3, w.x); fma2(acc[3][1], a3, w.y);
        }
    }
#pragma unroll
    for (int i = 0; i < 4; ++i) {
        int r = r0 + ty*4 + i;
        if (r < n) {
            int orow = scat ? scat[r] : r;
            float2 lo = up2(acc[i][0]), hi = up2(acc[i][1]);
            float4 o;
            o.x = lo.x + b[tx*4 + 0];
            o.y = lo.y + b[tx*4 + 1];
            o.z = hi.x + b[tx*4 + 2];
            o.w = hi.y + b[tx*4 + 3];
            if (relu) {
                o.x = fmaxf(o.x, 0.f); o.y = fmaxf(o.y, 0.f);
                o.z = fmaxf(o.z, 0.f); o.w = fmaxf(o.w, 0.f);
            }
            *reinterpret_cast<float4*>(&Y[(size_t)orow*64 + tx*4]) = o;
        }
    }
}

// ---------------- final linear: out = [h1|h2] @ lin_w + lin_b (f32x2) --------
__global__ void k_lin(const float* __restrict__ A0, const float* __restrict__ A1,
                      const float* __restrict__ W, const float* __restrict__ b,
                      float* __restrict__ C, int n)
{
    __shared__ float As[64][72];
    __shared__ float Ws[64][64];
    int tx = threadIdx.x, ty = threadIdx.y;
    int tid = ty*16 + tx;
    int r0 = blockIdx.x * 64;
    u64 acc[4][2] = {};
    for (int kt = 0; kt < 2; ++kt) {
        const float* A = (kt == 0) ? A0 : A1;
        __syncthreads();
        for (int idx = tid; idx < 64*64; idx += 256) {
            int row = idx >> 6, k = idx & 63;
            int gr = r0 + row;
            As[k][row] = (gr < n) ? A[(size_t)gr*64 + k] : 0.f;
        }
        for (int idx = tid; idx < 64*64; idx += 256) {
            int kr = idx >> 6, c = idx & 63;
            Ws[kr][c] = W[(size_t)(kt*64 + kr)*64 + c];
        }
        __syncthreads();
#pragma unroll 8
        for (int k = 0; k < 64; ++k) {
            float4 a = *reinterpret_cast<const float4*>(&As[k][ty*4]);
            ulonglong2 w = *reinterpret_cast<const ulonglong2*>(&Ws[k][tx*4]);
            u64 a0 = dup2(a.x), a1 = dup2(a.y), a2 = dup2(a.z), a3 = dup2(a.w);
            fma2(acc[0][0], a0, w.x); fma2(acc[0][1], a0, w.y);
            fma2(acc[1][0], a1, w.x); fma2(acc[1][1], a1, w.y);
            fma2(acc[2][0], a2, w.x); fma2(acc[2][1], a2, w.y);
            fma2(acc[3][0], a3, w.x); fma2(acc[3][1], a3, w.y);
        }
    }
#pragma unroll
    for (int i = 0; i < 4; ++i) {
        int gr = r0 + ty*4 + i;
        if (gr < n) {
            float2 lo = up2(acc[i][0]), hi = up2(acc[i][1]);
            float4 o;
            o.x = lo.x + b[tx*4 + 0];
            o.y = lo.y + b[tx*4 + 1];
            o.z = hi.x + b[tx*4 + 2];
            o.w = hi.y + b[tx*4 + 3];
            *reinterpret_cast<float4*>(&C[(size_t)gr*64 + tx*4]) = o;
        }
    }
}

// ---------------- host launcher ---------------------------------------------
extern "C" void kernel_launch(void* const* d_in, const int* in_sizes, int n_in,
                              void* d_out, int out_size)
{
    const float* x   = (const float*)d_in[0];
    const int*   ei  = (const int*)  d_in[1];
    const float* W0  = (const float*)d_in[2];
    const float* b0  = (const float*)d_in[3];
    const float* W1  = (const float*)d_in[4];
    const float* b1  = (const float*)d_in[5];
    const float* W2  = (const float*)d_in[6];
    const float* b2  = (const float*)d_in[7];
    const float* Wp  = (const float*)d_in[8];
    const float* bp  = (const float*)d_in[9];
    const float* c1w = (const float*)d_in[10];
    const float* c1b = (const float*)d_in[11];
    const float* c2w = (const float*)d_in[12];
    const float* c2b = (const float*)d_in[13];
    const float* lw  = (const float*)d_in[14];
    const float* lb  = (const float*)d_in[15];
    float* out = (float*)d_out;

    const int n = NN, E = NE;
    const int* src = ei;
    const int* dst = ei + E;

    float *p_tmp, *p_bufA, *p_bufB, *p_h1, *p_h2, *p_c1, *p_w1t, *p_w2t;
    int *p_sidx;
    cudaGetSymbolAddress((void**)&p_tmp,  g_tmp);
    cudaGetSymbolAddress((void**)&p_bufA, g_bufA);
    cudaGetSymbolAddress((void**)&p_bufB, g_bufB);
    cudaGetSymbolAddress((void**)&p_h1,   g_h1);
    cudaGetSymbolAddress((void**)&p_h2,   g_h2);
    cudaGetSymbolAddress((void**)&p_c1,   g_c1);
    cudaGetSymbolAddress((void**)&p_w1t,  g_w1t);
    cudaGetSymbolAddress((void**)&p_w2t,  g_w2t);
    cudaGetSymbolAddress((void**)&p_sidx, g_sidx);

    dim3 tg(16, 16);
    int  gb = (n + 63) / 64;
    int  ab = (n + 7) / 8;     // warp per node, 8 warps/block

    // ---- CSR build; k_gemm layer0 is independent, placed as 4th launch so
    //      the ncu capture window (skip 5 incl. ~2 harness launches) hits it ----
    k_zero <<<(n + 255)/256, 256>>>();
    k_deg  <<<(E + 255)/256, 256>>>(dst);
    k_scan1<<<NB, SCB>>>();
    k_gemm <<<gb, tg>>>(x, 128, W0, p_tmp, n);          // <-- profile target
    k_scan2<<<1, 128>>>();
    k_scan3<<<NB, SCB>>>();
    k_pad  <<<(MSORT - NN + 255)/256, 256>>>();
    k_fill <<<(E + 255)/256, 256>>>(src, dst);

    // ---- 3 GCN layers (layer 3 fuses the score projection) ----
    k_agg <<<ab, 256>>>(p_tmp, b0, p_bufA, 1, n, nullptr, nullptr);
    k_gemm<<<gb, tg>>>(p_bufA, 64, W1, p_tmp, n);
    k_agg <<<ab, 256>>>(p_tmp, b1, p_bufB, 1, n, nullptr, nullptr);
    k_gemm<<<gb, tg>>>(p_bufB, 64, W2, p_tmp, n);
    k_agg <<<ab, 256>>>(p_tmp, b2, p_h1, 0, n, Wp, bp);

    // ---- stable bitonic argsort (2048-span, R3-proven) ----
    k_localsort<<<MSORT/2048, 1024>>>();
    for (int k = 4096; k <= MSORT; k <<= 1) {
        for (int j = k >> 1; j >= 2048; j >>= 1)
            k_globalpass<<<MSORT/2048, 1024>>>(k, j);
        k_mergeshared<<<MSORT/2048, 1024>>>(k);
    }

    // ---- convs (conv1 gathers sorted_x on the fly, conv2 scatters back),
    //      final linear ----
    k_transw<<<(5*64*64 + 255)/256, 256>>>(c1w, p_w1t);
    k_transw<<<(5*64*64 + 255)/256, 256>>>(c2w, p_w2t);
    k_conv<<<gb, tg>>>(nullptr, p_w1t, c1b, p_c1, nullptr, 1, 1, n);
    k_conv<<<gb, tg>>>(p_c1,    p_w2t, c2b, p_h2, p_sidx, 0, 0, n);
    k_lin<<<gb, tg>>>(p_h1, p_h2, lw, lb, out, n);
}

// round 6
// speedup vs baseline: 1.2967x; 1.2192x over previous
#include <cuda_runtime.h>
#include <cstdint>
#include <math_constants.h>

#define NN 100000
#define NE 1600000
#define MSORT 131072   // next pow2 >= NN
#define SCB 1024
#define NB  ((NN + SCB - 1) / SCB)   // 98

// ---------------- scratch (static device globals; no allocations) ----------
__device__ float g_tmp [NN*64];
__device__ float g_bufA[NN*64];
__device__ float g_bufB[NN*64];
__device__ float g_h1  [NN*64];
__device__ float g_h2  [NN*64];
__device__ float g_c1  [NN*64];
__device__ float g_dinv[NN];
__device__ int   g_deg [NN];
__device__ int   g_fill[NN];
__device__ int   g_rowptr[NN+1];
__device__ int   g_part[NB+1];
__device__ int   g_col [NE];
__device__ float g_wgt [NE];
__device__ float g_key [MSORT];
__device__ int   g_sidx[MSORT];
__device__ float g_w1t [5*64*64];
__device__ float g_w2t [5*64*64];

// ---------------- f32x2 packed helpers --------------------------------------
typedef unsigned long long u64;
__device__ __forceinline__ u64 pk2(float a, float b)
{
    u64 r; asm("mov.b64 %0, {%1, %2};" : "=l"(r) : "f"(a), "f"(b)); return r;
}
__device__ __forceinline__ u64 dup2(float a) { return pk2(a, a); }
__device__ __forceinline__ void fma2(u64& d, u64 a, u64 b)
{
    asm("fma.rn.f32x2 %0, %1, %2, %0;" : "+l"(d) : "l"(a), "l"(b));
}
__device__ __forceinline__ float2 up2(u64 v)
{
    float2 f; asm("mov.b64 {%0, %1}, %2;" : "=f"(f.x), "=f"(f.y) : "l"(v)); return f;
}

// ---------------- init: zero degrees + pad sort keys -------------------------
__global__ void k_init()
{
    int i = blockIdx.x*blockDim.x + threadIdx.x;
    if (i < NN) g_deg[i] = 0;
    if (i >= NN && i < MSORT) { g_key[i] = CUDART_INF_F; g_sidx[i] = i; }
}

__global__ void k_deg(const int* __restrict__ dst)
{
    int e = blockIdx.x*blockDim.x + threadIdx.x;
    if (e < NE) atomicAdd(&g_deg[dst[e]], 1);
}

__global__ void k_scan1()
{
    __shared__ int s[SCB];
    int b = blockIdx.x, t = threadIdx.x;
    int i = b*SCB + t;
    int v = (i < NN) ? g_deg[i] : 0;
    s[t] = v;
    __syncthreads();
#pragma unroll
    for (int off = 1; off < SCB; off <<= 1) {
        int u = (t >= off) ? s[t - off] : 0;
        __syncthreads();
        s[t] += u;
        __syncthreads();
    }
    if (i < NN) g_rowptr[i] = s[t];
    if (t == SCB-1) g_part[b] = s[SCB-1];
}

__global__ void k_scan2()
{
    __shared__ int s[128];
    int t = threadIdx.x;
    int v = (t < NB) ? g_part[t] : 0;
    s[t] = v;
    __syncthreads();
#pragma unroll
    for (int off = 1; off < 128; off <<= 1) {
        int u = (t >= off) ? s[t - off] : 0;
        __syncthreads();
        s[t] += u;
        __syncthreads();
    }
    if (t < NB) g_part[t] = s[t] - v;
}

__global__ void k_scan3()
{
    int b = blockIdx.x, t = threadIdx.x;
    int i = b*SCB + t;
    if (i < NN) {
        int d = g_deg[i];
        g_rowptr[i] = g_rowptr[i] + g_part[b] - d;   // exclusive
        g_fill[i] = 0;
        g_dinv[i] = rsqrtf((float)(d + 1));          // +1 self loop
    }
    if (b == 0 && t == 0) g_rowptr[NN] = NE;
}

__global__ void k_fill(const int* __restrict__ src, const int* __restrict__ dst)
{
    int e = blockIdx.x*blockDim.x + threadIdx.x;
    if (e >= NE) return;
    int d = dst[e], s = src[e];
    int p = g_rowptr[d] + atomicAdd(&g_fill[d], 1);
    g_col[p] = s;
    g_wgt[p] = g_dinv[s] * g_dinv[d];
}

// ---------------- GEMM: C[n,64] = A[n,CI] @ W[CI,64] -------------------------
// [row][k] tiles: fill is STS-conflict-free + LDG-coalesced; reads broadcast.
__global__ void k_gemm(const float* __restrict__ A, int CI,
                       const float* __restrict__ W,
                       float* __restrict__ C, int n)
{
    __shared__ float As[64][64];    // [row][k]
    __shared__ float Ws[64][64];    // [k][col]
    int tx = threadIdx.x, ty = threadIdx.y;
    int tid = ty*16 + tx;
    int r0 = blockIdx.x * 64;
    u64 acc[4][2] = {};
    int ntiles = CI >> 6;
    for (int kt = 0; kt < ntiles; ++kt) {
        __syncthreads();
        for (int idx = tid; idx < 64*64; idx += 256) {
            int row = idx >> 6, k = idx & 63;
            int gr = r0 + row;
            As[row][k] = (gr < n) ? A[(size_t)gr*CI + kt*64 + k] : 0.f;
        }
        for (int idx = tid; idx < 64*64; idx += 256) {
            int kr = idx >> 6, c = idx & 63;
            Ws[kr][c] = W[(size_t)(kt*64 + kr)*64 + c];
        }
        __syncthreads();
#pragma unroll 4
        for (int k4 = 0; k4 < 64; k4 += 4) {
            float4 a0 = *reinterpret_cast<const float4*>(&As[ty*4+0][k4]);
            float4 a1 = *reinterpret_cast<const float4*>(&As[ty*4+1][k4]);
            float4 a2 = *reinterpret_cast<const float4*>(&As[ty*4+2][k4]);
            float4 a3 = *reinterpret_cast<const float4*>(&As[ty*4+3][k4]);
            float ar0[4] = {a0.x,a0.y,a0.z,a0.w};
            float ar1[4] = {a1.x,a1.y,a1.z,a1.w};
            float ar2[4] = {a2.x,a2.y,a2.z,a2.w};
            float ar3[4] = {a3.x,a3.y,a3.z,a3.w};
#pragma unroll
            for (int kk = 0; kk < 4; ++kk) {
                ulonglong2 w = *reinterpret_cast<const ulonglong2*>(&Ws[k4+kk][tx*4]);
                u64 b0 = dup2(ar0[kk]), b1 = dup2(ar1[kk]);
                u64 b2 = dup2(ar2[kk]), b3 = dup2(ar3[kk]);
                fma2(acc[0][0], b0, w.x); fma2(acc[0][1], b0, w.y);
                fma2(acc[1][0], b1, w.x); fma2(acc[1][1], b1, w.y);
                fma2(acc[2][0], b2, w.x); fma2(acc[2][1], b2, w.y);
                fma2(acc[3][0], b3, w.x); fma2(acc[3][1], b3, w.y);
            }
        }
    }
#pragma unroll
    for (int i = 0; i < 4; ++i) {
        int gr = r0 + ty*4 + i;
        if (gr < n) {
            float2 lo = up2(acc[i][0]), hi = up2(acc[i][1]);
            float4 o = make_float4(lo.x, lo.y, hi.x, hi.y);
            *reinterpret_cast<float4*>(&C[(size_t)gr*64 + tx*4]) = o;
        }
    }
}

// ---------------- GCN aggregation (warp per node, float2 lanes) --------------
// score != nullptr (last layer): also compute g_key[w] = h1[w].Wp + bp, g_sidx.
__global__ void k_agg(const float* __restrict__ T, const float* __restrict__ b,
                      float* __restrict__ O, int relu, int n,
                      const float* __restrict__ score_w, const float* __restrict__ score_b)
{
    int w    = (blockIdx.x*blockDim.x + threadIdx.x) >> 5;
    int lane = threadIdx.x & 31;
    if (w >= n) return;
    const float2* T2 = reinterpret_cast<const float2*>(T);
    int s = g_rowptr[w], e = g_rowptr[w+1];
    float a0 = 0.f, a1 = 0.f;
    int j = s;
    for (; j + 4 <= e; j += 4) {
        int   c0 = g_col[j],  c1 = g_col[j+1],  c2 = g_col[j+2],  c3 = g_col[j+3];
        float w0 = g_wgt[j],  w1 = g_wgt[j+1],  w2 = g_wgt[j+2],  w3 = g_wgt[j+3];
        float2 t0 = T2[(size_t)c0*32 + lane];
        float2 t1 = T2[(size_t)c1*32 + lane];
        float2 t2 = T2[(size_t)c2*32 + lane];
        float2 t3 = T2[(size_t)c3*32 + lane];
        a0 += w0*t0.x + w1*t1.x + w2*t2.x + w3*t3.x;
        a1 += w0*t0.y + w1*t1.y + w2*t2.y + w3*t3.y;
    }
    for (; j < e; ++j) {
        int c = g_col[j]; float ww = g_wgt[j];
        float2 t = T2[(size_t)c*32 + lane];
        a0 += ww * t.x;
        a1 += ww * t.y;
    }
    float di = g_dinv[w]; float sw = di*di;
    float2 ts = T2[(size_t)w*32 + lane];
    a0 += sw * ts.x;
    a1 += sw * ts.y;
    float2 bb = reinterpret_cast<const float2*>(b)[lane];
    a0 += bb.x;
    a1 += bb.y;
    if (relu) { a0 = fmaxf(a0, 0.f); a1 = fmaxf(a1, 0.f); }
    reinterpret_cast<float2*>(O)[(size_t)w*32 + lane] = make_float2(a0, a1);
    if (score_w) {
        float2 wp = reinterpret_cast<const float2*>(score_w)[lane];
        float p = a0*wp.x + a1*wp.y;
#pragma unroll
        for (int o = 16; o; o >>= 1) p += __shfl_xor_sync(0xffffffffu, p, o);
        if (lane == 0) { g_key[w] = p + score_b[0]; g_sidx[w] = w; }
    }
}

// ---------------- bitonic sort (stable via index tie-break) ------------------
__device__ __forceinline__ bool cmp_gt(float ka, int ia, float kb, int ib)
{
    return (ka > kb) || (ka == kb && ia > ib);
}
__device__ __forceinline__ void ce(float& ka, int& ia, float& kb, int& ib, bool asc)
{
    if (cmp_gt(ka, ia, kb, ib) == asc) {
        float tk = ka; ka = kb; kb = tk;
        int   ti = ia; ia = ib; ib = ti;
    }
}

__global__ void k_localsort()
{
    __shared__ float sk[2048];
    __shared__ int   si[2048];
    int t = threadIdx.x;
    int base = blockIdx.x * 2048;
    sk[t]        = g_key[base + t];        si[t]        = g_sidx[base + t];
    sk[t + 1024] = g_key[base + t + 1024]; si[t + 1024] = g_sidx[base + t + 1024];
    for (int k = 2; k <= 2048; k <<= 1) {
        for (int j = k >> 1; j > 0; j >>= 1) {
            __syncthreads();
            int i = ((t & ~(j-1)) << 1) | (t & (j-1));
            int p = i + j;
            bool asc = (((base + i) & k) == 0);
            float ki = sk[i], kp = sk[p];
            int   xi = si[i], xp = si[p];
            if (cmp_gt(ki, xi, kp, xp) == asc) {
                sk[i] = kp; sk[p] = ki; si[i] = xp; si[p] = xi;
            }
        }
    }
    __syncthreads();
    g_key[base + t]        = sk[t];        g_sidx[base + t]        = si[t];
    g_key[base + t + 1024] = sk[t + 1024]; g_sidx[base + t + 1024] = si[t + 1024];
}

// one global step j
__global__ void k_gp1(int k, int j)
{
    int t = blockIdx.x*blockDim.x + threadIdx.x;   // < MSORT/2
    int i = ((t & ~(j-1)) << 1) | (t & (j-1));
    int p = i + j;
    bool asc = ((i & k) == 0);
    float ki = g_key[i], kp = g_key[p];
    int   xi = g_sidx[i], xp = g_sidx[p];
    if (cmp_gt(ki, xi, kp, xp) == asc) {
        g_key[i] = kp; g_key[p] = ki; g_sidx[i] = xp; g_sidx[p] = xi;
    }
}

// two fused global steps (j, j/2): 4 elements/thread, self-contained quad
__global__ void k_gp2(int k, int j)
{
    int t = blockIdx.x*blockDim.x + threadIdx.x;   // < MSORT/4
    int q = j >> 1;
    int i0 = ((t & ~(q-1)) << 2) | (t & (q-1));
    float kk[4]; int xx[4];
#pragma unroll
    for (int m = 0; m < 4; ++m) { kk[m] = g_key[i0 + m*q]; xx[m] = g_sidx[i0 + m*q]; }
    bool asc = ((i0 & k) == 0);
    // step j = 2q: (0,2),(1,3)
    ce(kk[0],xx[0],kk[2],xx[2],asc); ce(kk[1],xx[1],kk[3],xx[3],asc);
    // step q: (0,1),(2,3)
    ce(kk[0],xx[0],kk[1],xx[1],asc); ce(kk[2],xx[2],kk[3],xx[3],asc);
#pragma unroll
    for (int m = 0; m < 4; ++m) { g_key[i0 + m*q] = kk[m]; g_sidx[i0 + m*q] = xx[m]; }
}

// three fused global steps (j, j/2, j/4): 8 elements/thread
__global__ void k_gp3(int k, int j)
{
    int t = blockIdx.x*blockDim.x + threadIdx.x;   // < MSORT/8
    int q = j >> 2;
    int i0 = ((t & ~(q-1)) << 3) | (t & (q-1));
    float kk[8]; int xx[8];
#pragma unroll
    for (int m = 0; m < 8; ++m) { kk[m] = g_key[i0 + m*q]; xx[m] = g_sidx[i0 + m*q]; }
    bool asc = ((i0 & k) == 0);
    // step j = 4q: (m, m+4)
#pragma unroll
    for (int m = 0; m < 4; ++m) ce(kk[m],xx[m],kk[m+4],xx[m+4],asc);
    // step 2q: (0,2),(1,3),(4,6),(5,7)
    ce(kk[0],xx[0],kk[2],xx[2],asc); ce(kk[1],xx[1],kk[3],xx[3],asc);
    ce(kk[4],xx[4],kk[6],xx[6],asc); ce(kk[5],xx[5],kk[7],xx[7],asc);
    // step q: (0,1),(2,3),(4,5),(6,7)
    ce(kk[0],xx[0],kk[1],xx[1],asc); ce(kk[2],xx[2],kk[3],xx[3],asc);
    ce(kk[4],xx[4],kk[5],xx[5],asc); ce(kk[6],xx[6],kk[7],xx[7],asc);
#pragma unroll
    for (int m = 0; m < 8; ++m) { g_key[i0 + m*q] = kk[m]; g_sidx[i0 + m*q] = xx[m]; }
}

__global__ void k_mergeshared(int k)
{
    __shared__ float sk[2048];
    __shared__ int   si[2048];
    int t = threadIdx.x;
    int base = blockIdx.x * 2048;
    sk[t]        = g_key[base + t];        si[t]        = g_sidx[base + t];
    sk[t + 1024] = g_key[base + t + 1024]; si[t + 1024] = g_sidx[base + t + 1024];
    bool asc = ((base & k) == 0);          // k >= 4096: constant per 2048-chunk
    for (int j = 1024; j > 0; j >>= 1) {
        __syncthreads();
        int i = ((t & ~(j-1)) << 1) | (t & (j-1));
        int p = i + j;
        float ki = sk[i], kp = sk[p];
        int   xi = si[i], xp = si[p];
        if (cmp_gt(ki, xi, kp, xp) == asc) {
            sk[i] = kp; sk[p] = ki; si[i] = xp; si[p] = xi;
        }
    }
    __syncthreads();
    g_key[base + t]        = sk[t];        g_sidx[base + t]        = si[t];
    g_key[base + t + 1024] = sk[t + 1024]; g_sidx[base + t + 1024] = si[t + 1024];
}

// ---------------- conv weight transpose: [co][ci][k] -> [k][ci][co] ----------
__global__ void k_transw(const float* __restrict__ w1, const float* __restrict__ w2)
{
    int t = blockIdx.x*blockDim.x + threadIdx.x;
    if (t >= 2*5*64*64) return;
    int which = t >= 5*64*64;
    int u = t - which*5*64*64;
    int co = u & 63;
    int ci = (u >> 6) & 63;
    int kk = u >> 12;
    float v = which ? w2[co*320 + ci*5 + kk] : w1[co*320 + ci*5 + kk];
    if (which) g_w2t[u] = v; else g_w1t[u] = v;
}

// ---------------- conv1d over ranks (K=5, pad=2, f32x2) ----------------------
// [rl][ci] tile (conflict-free fill); per-tap 16KB weight reload (occupancy).
// gather=1: input row r is g_key[r] * g_h1[g_sidx[r]][ci]  (fused buildsx)
__global__ void k_conv(const float* __restrict__ X, const float* __restrict__ Wt,
                       const float* __restrict__ b, float* __restrict__ Y,
                       const int* __restrict__ scat, int relu, int gather, int n)
{
    __shared__ float xs[68][64];   // [rl][ci], rl covers rows r0-2 .. r0+65
    __shared__ float ws[64][64];   // [ci][co] for current tap k
    int tx = threadIdx.x, ty = threadIdx.y;
    int tid = ty*16 + tx;
    int r0 = blockIdx.x * 64;
    for (int idx = tid; idx < 68*64; idx += 256) {
        int rl = idx >> 6, ci = idx & 63;
        int r = r0 - 2 + rl;
        float v = 0.f;
        if (r >= 0 && r < n) {
            if (gather) v = g_key[r] * g_h1[(size_t)g_sidx[r]*64 + ci];
            else        v = X[(size_t)r*64 + ci];
        }
        xs[rl][ci] = v;
    }
    u64 acc[4][2] = {};
    for (int k = 0; k < 5; ++k) {
        __syncthreads();
        for (int idx = tid; idx < 4096; idx += 256)
            ws[idx >> 6][idx & 63] = Wt[k*4096 + idx];
        __syncthreads();
#pragma unroll 4
        for (int c4 = 0; c4 < 64; c4 += 4) {
            float4 a0 = *reinterpret_cast<const float4*>(&xs[ty*4+0+k][c4]);
            float4 a1 = *reinterpret_cast<const float4*>(&xs[ty*4+1+k][c4]);
            float4 a2 = *reinterpret_cast<const float4*>(&xs[ty*4+2+k][c4]);
            float4 a3 = *reinterpret_cast<const float4*>(&xs[ty*4+3+k][c4]);
            float ar0[4] = {a0.x,a0.y,a0.z,a0.w};
            float ar1[4] = {a1.x,a1.y,a1.z,a1.w};
            float ar2[4] = {a2.x,a2.y,a2.z,a2.w};
            float ar3[4] = {a3.x,a3.y,a3.z,a3.w};
#pragma unroll
            for (int cc = 0; cc < 4; ++cc) {
                ulonglong2 w = *reinterpret_cast<const ulonglong2*>(&ws[c4+cc][tx*4]);
                u64 b0 = dup2(ar0[cc]), b1 = dup2(ar1[cc]);
                u64 b2 = dup2(ar2[cc]), b3 = dup2(ar3[cc]);
                fma2(acc[0][0], b0, w.x); fma2(acc[0][1], b0, w.y);
                fma2(acc[1][0], b1, w.x); fma2(acc[1][1], b1, w.y);
                fma2(acc[2][0], b2, w.x); fma2(acc[2][1], b2, w.y);
                fma2(acc[3][0], b3, w.x); fma2(acc[3][1], b3, w.y);
            }
        }
    }
#pragma unroll
    for (int i = 0; i < 4; ++i) {
        int r = r0 + ty*4 + i;
        if (r < n) {
            int orow = scat ? scat[r] : r;
            float2 lo = up2(acc[i][0]), hi = up2(acc[i][1]);
            float4 o;
            o.x = lo.x + b[tx*4 + 0];
            o.y = lo.y + b[tx*4 + 1];
            o.z = hi.x + b[tx*4 + 2];
            o.w = hi.y + b[tx*4 + 3];
            if (relu) {
                o.x = fmaxf(o.x, 0.f); o.y = fmaxf(o.y, 0.f);
                o.z = fmaxf(o.z, 0.f); o.w = fmaxf(o.w, 0.f);
            }
            *reinterpret_cast<float4*>(&Y[(size_t)orow*64 + tx*4]) = o;
        }
    }
}

// ---------------- final linear: out = [h1|h2] @ lin_w + lin_b (f32x2) --------
__global__ void k_lin(const float* __restrict__ A0, const float* __restrict__ A1,
                      const float* __restrict__ W, const float* __restrict__ b,
                      float* __restrict__ C, int n)
{
    __shared__ float As[64][64];   // [row][k]
    __shared__ float Ws[64][64];
    int tx = threadIdx.x, ty = threadIdx.y;
    int tid = ty*16 + tx;
    int r0 = blockIdx.x * 64;
    u64 acc[4][2] = {};
    for (int kt = 0; kt < 2; ++kt) {
        const float* A = (kt == 0) ? A0 : A1;
        __syncthreads();
        for (int idx = tid; idx < 64*64; idx += 256) {
            int row = idx >> 6, k = idx & 63;
            int gr = r0 + row;
            As[row][k] = (gr < n) ? A[(size_t)gr*64 + k] : 0.f;
        }
        for (int idx = tid; idx < 64*64; idx += 256) {
            int kr = idx >> 6, c = idx & 63;
            Ws[kr][c] = W[(size_t)(kt*64 + kr)*64 + c];
        }
        __syncthreads();
#pragma unroll 4
        for (int k4 = 0; k4 < 64; k4 += 4) {
            float4 a0 = *reinterpret_cast<const float4*>(&As[ty*4+0][k4]);
            float4 a1 = *reinterpret_cast<const float4*>(&As[ty*4+1][k4]);
            float4 a2 = *reinterpret_cast<const float4*>(&As[ty*4+2][k4]);
            float4 a3 = *reinterpret_cast<const float4*>(&As[ty*4+3][k4]);
            float ar0[4] = {a0.x,a0.y,a0.z,a0.w};
            float ar1[4] = {a1.x,a1.y,a1.z,a1.w};
            float ar2[4] = {a2.x,a2.y,a2.z,a2.w};
            float ar3[4] = {a3.x,a3.y,a3.z,a3.w};
#pragma unroll
            for (int kk = 0; kk < 4; ++kk) {
                ulonglong2 w = *reinterpret_cast<const ulonglong2*>(&Ws[k4+kk][tx*4]);
                u64 b0 = dup2(ar0[kk]), b1 = dup2(ar1[kk]);
                u64 b2 = dup2(ar2[kk]), b3 = dup2(ar3[kk]);
                fma2(acc[0][0], b0, w.x); fma2(acc[0][1], b0, w.y);
                fma2(acc[1][0], b1, w.x); fma2(acc[1][1], b1, w.y);
                fma2(acc[2][0], b2, w.x); fma2(acc[2][1], b2, w.y);
                fma2(acc[3][0], b3, w.x); fma2(acc[3][1], b3, w.y);
            }
        }
    }
#pragma unroll
    for (int i = 0; i < 4; ++i) {
        int gr = r0 + ty*4 + i;
        if (gr < n) {
            float2 lo = up2(acc[i][0]), hi = up2(acc[i][1]);
            float4 o;
            o.x = lo.x + b[tx*4 + 0];
            o.y = lo.y + b[tx*4 + 1];
            o.z = hi.x + b[tx*4 + 2];
            o.w = hi.y + b[tx*4 + 3];
            *reinterpret_cast<float4*>(&C[(size_t)gr*64 + tx*4]) = o;
        }
    }
}

// ---------------- host launcher ---------------------------------------------
extern "C" void kernel_launch(void* const* d_in, const int* in_sizes, int n_in,
                              void* d_out, int out_size)
{
    const float* x   = (const float*)d_in[0];
    const int*   ei  = (const int*)  d_in[1];
    const float* W0  = (const float*)d_in[2];
    const float* b0  = (const float*)d_in[3];
    const float* W1  = (const float*)d_in[4];
    const float* b1  = (const float*)d_in[5];
    const float* W2  = (const float*)d_in[6];
    const float* b2  = (const float*)d_in[7];
    const float* Wp  = (const float*)d_in[8];
    const float* bp  = (const float*)d_in[9];
    const float* c1w = (const float*)d_in[10];
    const float* c1b = (const float*)d_in[11];
    const float* c2w = (const float*)d_in[12];
    const float* c2b = (const float*)d_in[13];
    const float* lw  = (const float*)d_in[14];
    const float* lb  = (const float*)d_in[15];
    float* out = (float*)d_out;

    const int n = NN, E = NE;
    const int* src = ei;
    const int* dst = ei + E;

    float *p_tmp, *p_bufA, *p_bufB, *p_h1, *p_h2, *p_c1, *p_w1t, *p_w2t;
    int *p_sidx;
    cudaGetSymbolAddress((void**)&p_tmp,  g_tmp);
    cudaGetSymbolAddress((void**)&p_bufA, g_bufA);
    cudaGetSymbolAddress((void**)&p_bufB, g_bufB);
    cudaGetSymbolAddress((void**)&p_h1,   g_h1);
    cudaGetSymbolAddress((void**)&p_h2,   g_h2);
    cudaGetSymbolAddress((void**)&p_c1,   g_c1);
    cudaGetSymbolAddress((void**)&p_w1t,  g_w1t);
    cudaGetSymbolAddress((void**)&p_w2t,  g_w2t);
    cudaGetSymbolAddress((void**)&p_sidx, g_sidx);

    dim3 tg(16, 16);
    int  gb = (n + 63) / 64;
    int  ab = (n + 7) / 8;     // warp per node, 8 warps/block

    // ---- CSR build; layer-0 gemm kept as 4th launch (stable ncu slot) ----
    k_init <<<(MSORT + 255)/256, 256>>>();
    k_deg  <<<(E + 255)/256, 256>>>(dst);
    k_scan1<<<NB, SCB>>>();
    k_gemm <<<gb, tg>>>(x, 128, W0, p_tmp, n);          // <-- profile target
    k_scan2<<<1, 128>>>();
    k_scan3<<<NB, SCB>>>();
    k_fill <<<(E + 255)/256, 256>>>(src, dst);

    // ---- 3 GCN layers (layer 3 fuses the score projection) ----
    k_agg <<<ab, 256>>>(p_tmp, b0, p_bufA, 1, n, nullptr, nullptr);
    k_gemm<<<gb, tg>>>(p_bufA, 64, W1, p_tmp, n);
    k_agg <<<ab, 256>>>(p_tmp, b1, p_bufB, 1, n, nullptr, nullptr);
    k_gemm<<<gb, tg>>>(p_bufB, 64, W2, p_tmp, n);
    k_agg <<<ab, 256>>>(p_tmp, b2, p_h1, 0, n, Wp, bp);

    // ---- stable bitonic argsort (fused global steps: 9 global launches) ----
    k_localsort<<<MSORT/2048, 1024>>>();
    for (int k = 4096; k <= MSORT; k <<= 1) {
        int j = k >> 1;
        while (j >= 2048) {
            if (j >= 8192)      { k_gp3<<<MSORT/8/256, 256>>>(k, j); j >>= 3; }
            else if (j >= 4096) { k_gp2<<<MSORT/4/256, 256>>>(k, j); j >>= 2; }
            else                { k_gp1<<<MSORT/2/256, 256>>>(k, j); j >>= 1; }
        }
        k_mergeshared<<<MSORT/2048, 1024>>>(k);
    }

    // ---- convs (conv1 gathers sorted_x on the fly, conv2 scatters back),
    //      final linear ----
    k_transw<<<(2*5*64*64 + 255)/256, 256>>>(c1w, c2w);
    k_conv<<<gb, tg>>>(nullptr, p_w1t, c1b, p_c1, nullptr, 1, 1, n);
    k_conv<<<gb, tg>>>(p_c1,    p_w2t, c2b, p_h2, p_sidx, 0, 0, n);
    k_lin<<<gb, tg>>>(p_h1, p_h2, lw, lb, out, n);
}